// round 9
// baseline (speedup 1.0000x reference)
#include <cuda_runtime.h>
#include <cuda_fp16.h>
#include <cstdint>
#include <cstddef>

#define BDIM 64
#define TDIM 512
#define DDIM 512
#define HDIM 1024
#define ODIM 512
#define G3   3072
#define MROWS 32768            // B*T
#define RCTA 64                // recurrence CTAs (single wave)
#define RJ   16                // hidden units per recurrence CTA

// Scratch (device globals are the sanctioned no-alloc workaround)
__device__ float g_xall[(size_t)MROWS * G3];          // x projection, 402 MB
__device__ unsigned g_hfrag16[4][BDIM * HDIM / 2];    // h version ring (fp16 A-frags)
__device__ int g_prod[RCTA * 32];                     // producer epochs (128B-padded)
__device__ int g_cons[RCTA * 32];                     // consumer epochs (128B-padded)

__device__ __forceinline__ unsigned f2tf32(float x) {
    unsigned r;
    asm("cvt.rna.tf32.f32 %0, %1;" : "=r"(r) : "f"(x));
    return r;
}

__device__ __forceinline__ unsigned packh2(float a, float b) {
    __half2 h = __floats2half2_rn(a, b);
    return *(unsigned*)&h;
}

__device__ __forceinline__ int ld_acq(const int* p) {
    int v;
    asm volatile("ld.global.acquire.gpu.s32 %0, [%1];" : "=r"(v) : "l"(p) : "memory");
    return v;
}
__device__ __forceinline__ void st_rel(int* p, int v) {
    asm volatile("st.global.release.gpu.s32 [%0], %1;" :: "l"(p), "r"(v) : "memory");
}

__device__ __forceinline__ void mma_tf32_k8(float* d,
    unsigned a0, unsigned a1, unsigned a2, unsigned a3,
    unsigned b0, unsigned b1)
{
    asm volatile(
        "mma.sync.aligned.m16n8k8.row.col.f32.tf32.tf32.f32 "
        "{%0,%1,%2,%3}, {%4,%5,%6,%7}, {%8,%9}, {%0,%1,%2,%3};\n"
        : "+f"(d[0]), "+f"(d[1]), "+f"(d[2]), "+f"(d[3])
        : "r"(a0), "r"(a1), "r"(a2), "r"(a3), "r"(b0), "r"(b1));
}

__device__ __forceinline__ void mma_f16_k16(float* d,
    unsigned a0, unsigned a1, unsigned a2, unsigned a3,
    unsigned b0, unsigned b1)
{
    asm volatile(
        "mma.sync.aligned.m16n8k16.row.col.f32.f16.f16.f32 "
        "{%0,%1,%2,%3}, {%4,%5,%6,%7}, {%8,%9}, {%0,%1,%2,%3};\n"
        : "+f"(d[0]), "+f"(d[1]), "+f"(d[2]), "+f"(d[3])
        : "r"(a0), "r"(a1), "r"(a2), "r"(a3), "r"(b0), "r"(b1));
}

__device__ __forceinline__ float sigmoidf_(float x) {
    return 1.0f / (1.0f + __expf(-x));
}
__device__ __forceinline__ float tanhf_(float x) {
    x = fminf(fmaxf(x, -15.0f), 15.0f);
    float e = __expf(-2.0f * x);
    return (1.0f - e) / (1.0f + e);
}

// One dummy launch keeps the recurrence kernel at ncu's -s 5 -c 1 slot.
__global__ void dummy_kernel() {}

// ---------------------------------------------------------------------------
// Generic NT GEMM: C[M,N] = A[M,K](rm) * B[N,K](rm)^T + bias[N]
// ---------------------------------------------------------------------------
__global__ __launch_bounds__(256) void gemm_nt_kernel(
    const float* __restrict__ A, const float* __restrict__ B,
    const float* __restrict__ bias, float* __restrict__ C,
    int N, int K)
{
    __shared__ unsigned As[32][132];
    __shared__ unsigned Bs[32][132];
    const int tid  = threadIdx.x;
    const int lane = tid & 31;
    const int warp = tid >> 5;
    const int wm = warp & 3;
    const int wn = warp >> 2;
    const int g = lane >> 2;
    const int c = lane & 3;
    const int bm = blockIdx.y, bn = blockIdx.x;
    const float* Ab = A + (size_t)bm * 128 * K;
    const float* Bb = B + (size_t)bn * 128 * K;

    float acc[2][8][4];
#pragma unroll
    for (int i = 0; i < 2; i++)
#pragma unroll
        for (int j = 0; j < 8; j++)
#pragma unroll
            for (int e = 0; e < 4; e++) acc[i][j][e] = 0.0f;

    for (int k0 = 0; k0 < K; k0 += 32) {
        __syncthreads();
#pragma unroll
        for (int p = 0; p < 4; p++) {
            int flat = p * 256 + tid;
            int row = flat >> 3;
            int ks = (flat & 7) * 4;
            float4 va = *(const float4*)(Ab + (size_t)row * K + k0 + ks);
            As[ks + 0][row] = f2tf32(va.x);
            As[ks + 1][row] = f2tf32(va.y);
            As[ks + 2][row] = f2tf32(va.z);
            As[ks + 3][row] = f2tf32(va.w);
            float4 vb = *(const float4*)(Bb + (size_t)row * K + k0 + ks);
            Bs[ks + 0][row] = f2tf32(vb.x);
            Bs[ks + 1][row] = f2tf32(vb.y);
            Bs[ks + 2][row] = f2tf32(vb.z);
            Bs[ks + 3][row] = f2tf32(vb.w);
        }
        __syncthreads();
#pragma unroll
        for (int ks = 0; ks < 32; ks += 8) {
            unsigned a[2][4], b[8][2];
#pragma unroll
            for (int mt = 0; mt < 2; mt++) {
                int mb = wm * 32 + mt * 16;
                a[mt][0] = As[ks + c][mb + g];
                a[mt][1] = As[ks + c][mb + g + 8];
                a[mt][2] = As[ks + c + 4][mb + g];
                a[mt][3] = As[ks + c + 4][mb + g + 8];
            }
#pragma unroll
            for (int nt = 0; nt < 8; nt++) {
                int col = wn * 64 + nt * 8 + g;
                b[nt][0] = Bs[ks + c][col];
                b[nt][1] = Bs[ks + c + 4][col];
            }
#pragma unroll
            for (int mt = 0; mt < 2; mt++)
#pragma unroll
                for (int nt = 0; nt < 8; nt++)
                    mma_tf32_k8(acc[mt][nt], a[mt][0], a[mt][1], a[mt][2], a[mt][3],
                                b[nt][0], b[nt][1]);
        }
    }

#pragma unroll
    for (int mt = 0; mt < 2; mt++) {
        int row = bm * 128 + wm * 32 + mt * 16 + g;
#pragma unroll
        for (int nt = 0; nt < 8; nt++) {
            int col = bn * 128 + wn * 64 + nt * 8 + 2 * c;
            float b0 = bias[col], b1 = bias[col + 1];
            C[(size_t)row * N + col]           = acc[mt][nt][0] + b0;
            C[(size_t)row * N + col + 1]       = acc[mt][nt][1] + b1;
            C[(size_t)(row + 8) * N + col]     = acc[mt][nt][2] + b0;
            C[(size_t)(row + 8) * N + col + 1] = acc[mt][nt][3] + b1;
        }
    }
}

// ---------------------------------------------------------------------------
// Persistent GRU recurrence, fp16 / fp32-acc, NO global barrier.
// Dataflow: CTA b is the sole producer of a-frag slice kb=b. Version v of h
// lives in g_hfrag16[v&3]; step t consumes version t, produces version t+1.
// Consumers poll prod[kb] >= t per 8-kb ring-refill group (flag loads software-
// pipelined so the fast path overlaps MMA). WAR guard: before writing version
// t+1 (overwrites t-3), all cons[] >= t-2 (3-step slack, off critical path).
// Reduction SMEM double-buffered so kh=1 warps run ahead into step t+1.
// ---------------------------------------------------------------------------
extern __shared__ unsigned rec_smem[];   // Whs16[24576] + red[2][3200 floats]

__device__ __forceinline__ void load_x(int t, int b0r, int b1r, int j0, int c,
                                       float2 xv[3][2][2])
{
#pragma unroll
    for (int gi = 0; gi < 3; gi++)
#pragma unroll
        for (int jh = 0; jh < 2; jh++) {
            int jj = j0 + jh * 8 + 2 * c;
            xv[gi][jh][0] = *(const float2*)&g_xall[((size_t)b0r * TDIM + t) * G3 + gi * HDIM + jj];
            xv[gi][jh][1] = *(const float2*)&g_xall[((size_t)b1r * TDIM + t) * G3 + gi * HDIM + jj];
        }
}

__global__ __launch_bounds__(256, 1) void gru_rec_kernel(
    const float* __restrict__ Wh, const float* __restrict__ bh,
    float* __restrict__ hiddens)
{
    unsigned* Whs = rec_smem;                       // [kb64][gate3][jh2][lane32][2]
    float* redb = (float*)(rec_smem + 24576);       // [2][mt4*lane32][25]
    const int tid  = threadIdx.x;
    const int lane = tid & 31;
    const int warp = tid >> 5;
    const int mt = warp & 3;        // batch quarter (16 rows)
    const int kh = warp >> 2;       // K half (0..1)
    const int g = lane >> 2, c = lane & 3;
    const int j0 = blockIdx.x * RJ;
    const int bid = blockIdx.x;

    // Load Wh slice -> SMEM in fp16 B-fragment order, once.
    for (int flat = tid; flat < 64 * 6 * 32; flat += 256) {
        int kb = flat / 192, rem = flat % 192;
        int gi = rem >> 6;
        int jh = (rem >> 5) & 1;
        int ln = rem & 31;
        int gg = ln >> 2, cc = ln & 3;
        const float* wp = Wh + (size_t)(gi * HDIM + j0 + jh * 8 + gg) * HDIM + kb * 16 + 2 * cc;
        Whs[flat * 2 + 0] = packh2(wp[0], wp[1]);
        Whs[flat * 2 + 1] = packh2(wp[8], wp[9]);
    }

    const int b0r = mt * 16 + g, b1r = b0r + 8;
    float bhv[3][2][2];
#pragma unroll
    for (int gi = 0; gi < 3; gi++)
#pragma unroll
        for (int jh = 0; jh < 2; jh++) {
            int jj = j0 + jh * 8 + 2 * c;
            bhv[gi][jh][0] = bh[gi * HDIM + jj];
            bhv[gi][jh][1] = bh[gi * HDIM + jj + 1];
        }

    float hpr[2][4];
#pragma unroll
    for (int jh = 0; jh < 2; jh++)
#pragma unroll
        for (int e = 0; e < 4; e++) hpr[jh][e] = 0.0f;

    __syncthreads();

    for (int t = 0; t < TDIM; t++) {
        // x_t loads issued early; DRAM latency hidden behind the MMA loop.
        float2 xv[3][2][2];
        if (kh == 0) load_x(t, b0r, b1r, j0, c, xv);

        float acc[3][2][4];
#pragma unroll
        for (int gi = 0; gi < 3; gi++)
#pragma unroll
            for (int jh = 0; jh < 2; jh++)
#pragma unroll
                for (int e = 0; e < 4; e++) acc[gi][jh][e] = 0.0f;

        // ---- MMA loop over this warp's 32 kb slices with dataflow polling.
        const unsigned* hfp = g_hfrag16[t & 3] + kh * 16384 + ((mt * 32 + lane) << 2);
        const int pb = kh * 32;     // producer CTA base for this warp

        // group 0 gate (producers pb..pb+7 must have published version t)
        if (lane < 8)
            while (ld_acq(&g_prod[(pb + lane) * 32]) < t) __nanosleep(20);
        __syncwarp();
        // preload group-1 flags (checked at base=0; latency overlaps ring fill)
        int fl = t;
        if (lane < 8) fl = ld_acq(&g_prod[(pb + 8 + lane) * 32]);

        uint4 ring[8];
#pragma unroll
        for (int i = 0; i < 8; i++)
            ring[i] = __ldcg((const uint4*)(hfp + i * 512));

        for (int base = 0; base < 32; base += 8) {
            if (base < 24) {
                // gate group base/8+1 (its kbs are refilled during this batch)
                if (lane < 8)
                    while (fl < t) {
                        __nanosleep(20);
                        fl = ld_acq(&g_prod[(pb + base + 8 + lane) * 32]);
                    }
                __syncwarp();
            }
            // preload the following group's flags (consumed next batch)
            int fln = t;
            if (base < 16 && lane < 8)
                fln = ld_acq(&g_prod[(pb + base + 16 + lane) * 32]);
#pragma unroll
            for (int u = 0; u < 8; u++) {
                const int it = base + u;
                uint4 a = ring[u];
                if (it < 24)
                    ring[u] = __ldcg((const uint4*)(hfp + (it + 8) * 512));
                const int kb = pb + it;
                const unsigned* wk = Whs + kb * 384 + lane * 2;
#pragma unroll
                for (int gi = 0; gi < 3; gi++)
#pragma unroll
                    for (int jh = 0; jh < 2; jh++) {
                        uint2 b = *(const uint2*)(wk + (gi * 2 + jh) * 64);
                        mma_f16_k16(acc[gi][jh], a.x, a.y, a.z, a.w, b.x, b.y);
                    }
            }
            fl = fln;
        }

        // ---- 2-way K reduction (double-buffered by t&1).
        float* red = redb + (t & 1) * 3200;
        if (kh == 1) {
            float* rp = red + (mt * 32 + lane) * 25;
#pragma unroll
            for (int gi = 0; gi < 3; gi++)
#pragma unroll
                for (int jh = 0; jh < 2; jh++)
#pragma unroll
                    for (int e = 0; e < 4; e++) rp[gi * 8 + jh * 4 + e] = acc[gi][jh][e];
        }
        __syncthreads();
        // All warps' a-frag reads for version t are complete here.
        if (tid == 0) st_rel(&g_cons[bid * 32], t + 1);

        if (kh == 0) {
            const float* rp = red + (mt * 32 + lane) * 25;
            float hy[2][4];
#pragma unroll
            for (int jh = 0; jh < 2; jh++)
#pragma unroll
                for (int e = 0; e < 4; e++) {
                    int part = e & 1, row = e >> 1;
                    float pr = acc[0][jh][e] + rp[0 * 8 + jh * 4 + e] + bhv[0][jh][part];
                    float pu = acc[1][jh][e] + rp[1 * 8 + jh * 4 + e] + bhv[1][jh][part];
                    float pn = acc[2][jh][e] + rp[2 * 8 + jh * 4 + e] + bhv[2][jh][part];
                    float xr = part ? xv[0][jh][row].y : xv[0][jh][row].x;
                    float xu = part ? xv[1][jh][row].y : xv[1][jh][row].x;
                    float xn = part ? xv[2][jh][row].y : xv[2][jh][row].x;
                    float rg = sigmoidf_(xr + pr);
                    float ug = sigmoidf_(xu + pu);
                    float ng = tanhf_(xn + rg * pn);
                    hy[jh][e] = ug * hpr[jh][e] + (1.0f - ug) * ng;
                    hpr[jh][e] = hy[jh][e];
                }

            // WAR guard: version t+1 overwrites t-3; need all cons >= t-2.
            if (mt == 0) {
                const int need = t - 2;
                while (ld_acq(&g_cons[lane * 32]) < need) __nanosleep(20);
                while (ld_acq(&g_cons[(lane + 32) * 32]) < need) __nanosleep(20);
            }
            asm volatile("bar.sync 1, 128;" ::: "memory");

            // Publish fp16 A-frag slice (one STG.128 per thread).
            uint4 w;
            w.x = packh2(hy[0][0], hy[0][1]);
            w.y = packh2(hy[0][2], hy[0][3]);
            w.z = packh2(hy[1][0], hy[1][1]);
            w.w = packh2(hy[1][2], hy[1][3]);
            unsigned* nf = g_hfrag16[(t + 1) & 3] + (((bid * 4 + mt) * 32 + lane) << 2);
            *(uint4*)nf = w;

            asm volatile("bar.sync 1, 128;" ::: "memory");
            if (tid == 0) st_rel(&g_prod[bid * 32], t + 1);

            // Off the critical path: hiddens output.
#pragma unroll
            for (int jh = 0; jh < 2; jh++) {
                int jj = j0 + jh * 8 + 2 * c;
                *(float2*)&hiddens[((size_t)b0r * TDIM + t) * HDIM + jj] =
                    make_float2(hy[jh][0], hy[jh][1]);
                *(float2*)&hiddens[((size_t)b1r * TDIM + t) * HDIM + jj] =
                    make_float2(hy[jh][2], hy[jh][3]);
            }
        }
        // No CTA-wide end-of-step sync: red is double-buffered, kh=1 warps
        // run ahead into step t+1 gated only by prod flags.
    }
}

__global__ void rec_init_kernel() {
    int i = blockIdx.x * blockDim.x + threadIdx.x;
    if (i < RCTA * 32) { g_prod[i] = 0; g_cons[i] = 0; }
    if (i < BDIM * HDIM / 2) g_hfrag16[0][i] = 0u;   // h0 = 0 (version 0)
}

extern "C" void kernel_launch(void* const* d_in, const int* in_sizes, int n_in,
                              void* d_out, int out_size)
{
    (void)in_sizes; (void)n_in; (void)out_size;
    const float* inputs = (const float*)d_in[0];
    const float* Wx = (const float*)d_in[1];
    const float* bx = (const float*)d_in[2];
    const float* Wh = (const float*)d_in[3];
    const float* bh = (const float*)d_in[4];
    const float* Wo = (const float*)d_in[5];
    const float* bo = (const float*)d_in[6];

    float* hiddens = (float*)d_out;                       // (B,T,H)
    float* proj    = hiddens + (size_t)MROWS * HDIM;      // (B,T,O)

    float* xall = nullptr;
    cudaGetSymbolAddress((void**)&xall, g_xall);

    // ncu alignment (harness pre-injects 2 launches; REC lands at -s 5 -c 1)
    dummy_kernel<<<1, 32>>>();

    // Phase 0: reset flags + zero h0 fragments (every launch/replay)
    rec_init_kernel<<<256, 256>>>();

    // Phase 1: x_all = inputs @ Wx^T + bx   (M=32768, N=3072, K=512)
    gemm_nt_kernel<<<dim3(G3 / 128, MROWS / 128), 256>>>(inputs, Wx, bx, xall, G3, DDIM);

    // Phase 2: persistent GRU recurrence -> hiddens (in d_out)
    const int rec_smem_bytes = 24576 * 4 + 2 * 3200 * 4;  // 123,904 B
    cudaFuncSetAttribute(gru_rec_kernel, cudaFuncAttributeMaxDynamicSharedMemorySize, rec_smem_bytes);
    gru_rec_kernel<<<RCTA, 256, rec_smem_bytes>>>(Wh, bh, hiddens);

    // Phase 3: out = hiddens @ Wo^T + bo   (M=32768, N=512, K=1024)
    gemm_nt_kernel<<<dim3(ODIM / 128, MROWS / 128), 256>>>(hiddens, Wo, bo, proj, ODIM, HDIM);
}

// round 10
// speedup vs baseline: 1.0858x; 1.0858x over previous
#include <cuda_runtime.h>
#include <cuda_fp16.h>
#include <cstdint>
#include <cstddef>

#define BDIM 64
#define TDIM 512
#define DDIM 512
#define HDIM 1024
#define ODIM 512
#define G3   3072
#define MROWS 32768            // B*T
#define RCTA 64                // recurrence CTAs (single wave)
#define RJ   16                // hidden units per recurrence CTA

// Scratch (device globals are the sanctioned no-alloc workaround)
__device__ float g_xall[(size_t)MROWS * G3];          // x projection, 402 MB
__device__ unsigned g_hfA[2][16384];                  // stream A h ping-pong (fp16 A-frags, 32xH)
__device__ unsigned g_hfB[2][16384];                  // stream B h ping-pong
__device__ int g_sync[128];                           // [0]=countA [32]=flagA [64]=countB [96]=flagB

__device__ __forceinline__ unsigned f2tf32(float x) {
    unsigned r;
    asm("cvt.rna.tf32.f32 %0, %1;" : "=r"(r) : "f"(x));
    return r;
}

__device__ __forceinline__ unsigned packh2(float a, float b) {
    __half2 h = __floats2half2_rn(a, b);
    return *(unsigned*)&h;
}

__device__ __forceinline__ int ld_acq(const int* p) {
    int v;
    asm volatile("ld.global.acquire.gpu.s32 %0, [%1];" : "=r"(v) : "l"(p) : "memory");
    return v;
}

__device__ __forceinline__ void mma_tf32_k8(float* d,
    unsigned a0, unsigned a1, unsigned a2, unsigned a3,
    unsigned b0, unsigned b1)
{
    asm volatile(
        "mma.sync.aligned.m16n8k8.row.col.f32.tf32.tf32.f32 "
        "{%0,%1,%2,%3}, {%4,%5,%6,%7}, {%8,%9}, {%0,%1,%2,%3};\n"
        : "+f"(d[0]), "+f"(d[1]), "+f"(d[2]), "+f"(d[3])
        : "r"(a0), "r"(a1), "r"(a2), "r"(a3), "r"(b0), "r"(b1));
}

__device__ __forceinline__ void mma_f16_k16(float* d,
    unsigned a0, unsigned a1, unsigned a2, unsigned a3,
    unsigned b0, unsigned b1)
{
    asm volatile(
        "mma.sync.aligned.m16n8k16.row.col.f32.f16.f16.f32 "
        "{%0,%1,%2,%3}, {%4,%5,%6,%7}, {%8,%9}, {%0,%1,%2,%3};\n"
        : "+f"(d[0]), "+f"(d[1]), "+f"(d[2]), "+f"(d[3])
        : "r"(a0), "r"(a1), "r"(a2), "r"(a3), "r"(b0), "r"(b1));
}

__device__ __forceinline__ float sigmoidf_(float x) {
    return 1.0f / (1.0f + __expf(-x));
}
__device__ __forceinline__ float tanhf_(float x) {
    x = fminf(fmaxf(x, -15.0f), 15.0f);
    float e = __expf(-2.0f * x);
    return (1.0f - e) / (1.0f + e);
}

// One dummy launch keeps the recurrence kernel at ncu's -s 5 -c 1 slot.
__global__ void dummy_kernel() {}

// ---------------------------------------------------------------------------
// Generic NT GEMM: C[M,N] = A[M,K](rm) * B[N,K](rm)^T + bias[N]  (unchanged)
// ---------------------------------------------------------------------------
__global__ __launch_bounds__(256) void gemm_nt_kernel(
    const float* __restrict__ A, const float* __restrict__ B,
    const float* __restrict__ bias, float* __restrict__ C,
    int N, int K)
{
    __shared__ unsigned As[32][132];
    __shared__ unsigned Bs[32][132];
    const int tid  = threadIdx.x;
    const int lane = tid & 31;
    const int warp = tid >> 5;
    const int wm = warp & 3;
    const int wn = warp >> 2;
    const int g = lane >> 2;
    const int c = lane & 3;
    const int bm = blockIdx.y, bn = blockIdx.x;
    const float* Ab = A + (size_t)bm * 128 * K;
    const float* Bb = B + (size_t)bn * 128 * K;

    float acc[2][8][4];
#pragma unroll
    for (int i = 0; i < 2; i++)
#pragma unroll
        for (int j = 0; j < 8; j++)
#pragma unroll
            for (int e = 0; e < 4; e++) acc[i][j][e] = 0.0f;

    for (int k0 = 0; k0 < K; k0 += 32) {
        __syncthreads();
#pragma unroll
        for (int p = 0; p < 4; p++) {
            int flat = p * 256 + tid;
            int row = flat >> 3;
            int ks = (flat & 7) * 4;
            float4 va = *(const float4*)(Ab + (size_t)row * K + k0 + ks);
            As[ks + 0][row] = f2tf32(va.x);
            As[ks + 1][row] = f2tf32(va.y);
            As[ks + 2][row] = f2tf32(va.z);
            As[ks + 3][row] = f2tf32(va.w);
            float4 vb = *(const float4*)(Bb + (size_t)row * K + k0 + ks);
            Bs[ks + 0][row] = f2tf32(vb.x);
            Bs[ks + 1][row] = f2tf32(vb.y);
            Bs[ks + 2][row] = f2tf32(vb.z);
            Bs[ks + 3][row] = f2tf32(vb.w);
        }
        __syncthreads();
#pragma unroll
        for (int ks = 0; ks < 32; ks += 8) {
            unsigned a[2][4], b[8][2];
#pragma unroll
            for (int mt = 0; mt < 2; mt++) {
                int mb = wm * 32 + mt * 16;
                a[mt][0] = As[ks + c][mb + g];
                a[mt][1] = As[ks + c][mb + g + 8];
                a[mt][2] = As[ks + c + 4][mb + g];
                a[mt][3] = As[ks + c + 4][mb + g + 8];
            }
#pragma unroll
            for (int nt = 0; nt < 8; nt++) {
                int col = wn * 64 + nt * 8 + g;
                b[nt][0] = Bs[ks + c][col];
                b[nt][1] = Bs[ks + c + 4][col];
            }
#pragma unroll
            for (int mt = 0; mt < 2; mt++)
#pragma unroll
                for (int nt = 0; nt < 8; nt++)
                    mma_tf32_k8(acc[mt][nt], a[mt][0], a[mt][1], a[mt][2], a[mt][3],
                                b[nt][0], b[nt][1]);
        }
    }

#pragma unroll
    for (int mt = 0; mt < 2; mt++) {
        int row = bm * 128 + wm * 32 + mt * 16 + g;
#pragma unroll
        for (int nt = 0; nt < 8; nt++) {
            int col = bn * 128 + wn * 64 + nt * 8 + 2 * c;
            float b0 = bias[col], b1 = bias[col + 1];
            C[(size_t)row * N + col]           = acc[mt][nt][0] + b0;
            C[(size_t)row * N + col + 1]       = acc[mt][nt][1] + b1;
            C[(size_t)(row + 8) * N + col]     = acc[mt][nt][2] + b0;
            C[(size_t)(row + 8) * N + col + 1] = acc[mt][nt][3] + b1;
        }
    }
}

// ---------------------------------------------------------------------------
// Persistent GRU recurrence: TWO batch streams (A = rows 0..31, B = 32..63)
// software-pipelined so each stream's barrier wait hides behind the other
// stream's MMA phase. 64 CTAs, 256 threads: mt = warp&1 (16-row m-tile),
// kh = warp>>1 (K quarter, 16 k16-iters). Wh SMEM-resident fp16 B-frags
// (96KB, shared by both streams). Per stream: fp16 A-frag ping-pong in GMEM,
// count+flag barrier (R8-proven). Gates: bar2 (flagB>=t before MMA_B),
// bar3 (flagA>=t+1 before next MMA_A); pollers are warp2/warp3 lane 0.
// ---------------------------------------------------------------------------
extern __shared__ unsigned rec_smem[];   // Whs16[24576] + redA[4800] + redB[4800]

struct EpiState {
    float2 xv[3][2][2];
    float  hpr[2][4];
};

__device__ __forceinline__ void load_x(int t, int b0g, int b1g, int j0, int c,
                                       float2 xv[3][2][2])
{
#pragma unroll
    for (int gi = 0; gi < 3; gi++)
#pragma unroll
        for (int jh = 0; jh < 2; jh++) {
            int jj = j0 + jh * 8 + 2 * c;
            xv[gi][jh][0] = *(const float2*)&g_xall[((size_t)b0g * TDIM + t) * G3 + gi * HDIM + jj];
            xv[gi][jh][1] = *(const float2*)&g_xall[((size_t)b1g * TDIM + t) * G3 + gi * HDIM + jj];
        }
}

// MMA over one stream's h version (16 kb slices for this warp's K quarter).
__device__ __forceinline__ void mma_phase(const unsigned* __restrict__ hbase,
                                          const unsigned* __restrict__ Whs,
                                          int mt, int kh, int lane,
                                          float acc[3][2][4])
{
#pragma unroll
    for (int gi = 0; gi < 3; gi++)
#pragma unroll
        for (int jh = 0; jh < 2; jh++)
#pragma unroll
            for (int e = 0; e < 4; e++) acc[gi][jh][e] = 0.0f;

    const unsigned* hfp = hbase + (kh * 16) * 256 + mt * 128 + (lane << 2);
    uint4 ring[8];
#pragma unroll
    for (int i = 0; i < 8; i++)
        ring[i] = __ldcg((const uint4*)(hfp + i * 256));

#pragma unroll
    for (int base = 0; base < 16; base += 8) {
#pragma unroll
        for (int u = 0; u < 8; u++) {
            const int it = base + u;
            uint4 a = ring[u];
            if (it < 8)
                ring[u] = __ldcg((const uint4*)(hfp + (it + 8) * 256));
            const int kb = kh * 16 + it;
            const unsigned* wk = Whs + kb * 384 + lane * 2;
#pragma unroll
            for (int gi = 0; gi < 3; gi++)
#pragma unroll
                for (int jh = 0; jh < 2; jh++) {
                    uint2 b = *(const uint2*)(wk + (gi * 2 + jh) * 64);
                    mma_f16_k16(acc[gi][jh], a.x, a.y, a.z, a.w, b.x, b.y);
                }
        }
    }
}

// Epilogue for one stream (kh==0 warps only): 3-way red fan-in, gate math,
// h publish (fp16 A-frag, one STG.128), returns hy for deferred hiddens STG.
__device__ __forceinline__ void epilogue(float acc[3][2][4], const float* red,
                                         EpiState& st, const float bhv[3][2][2],
                                         int mt, int lane, unsigned* pubbuf,
                                         int bid, int c, float hy[2][4])
{
    const int r = mt * 32 + lane;
#pragma unroll
    for (int s = 0; s < 3; s++) {
        const float* rp = red + (s * 64 + r) * 25;
#pragma unroll
        for (int gi = 0; gi < 3; gi++)
#pragma unroll
            for (int jh = 0; jh < 2; jh++)
#pragma unroll
                for (int e = 0; e < 4; e++)
                    acc[gi][jh][e] += rp[gi * 8 + jh * 4 + e];
    }
#pragma unroll
    for (int jh = 0; jh < 2; jh++)
#pragma unroll
        for (int e = 0; e < 4; e++) {
            int part = e & 1, row = e >> 1;
            float pr = acc[0][jh][e] + bhv[0][jh][part];
            float pu = acc[1][jh][e] + bhv[1][jh][part];
            float pn = acc[2][jh][e] + bhv[2][jh][part];
            float xr = part ? st.xv[0][jh][row].y : st.xv[0][jh][row].x;
            float xu = part ? st.xv[1][jh][row].y : st.xv[1][jh][row].x;
            float xn = part ? st.xv[2][jh][row].y : st.xv[2][jh][row].x;
            float rg = sigmoidf_(xr + pr);
            float ug = sigmoidf_(xu + pu);
            float ng = tanhf_(xn + rg * pn);
            hy[jh][e] = ug * st.hpr[jh][e] + (1.0f - ug) * ng;
            st.hpr[jh][e] = hy[jh][e];
        }
    uint4 w;
    w.x = packh2(hy[0][0], hy[0][1]);
    w.y = packh2(hy[0][2], hy[0][3]);
    w.z = packh2(hy[1][0], hy[1][1]);
    w.w = packh2(hy[1][2], hy[1][3]);
    *(uint4*)(pubbuf + (bid * 2 + mt) * 128 + (lane << 2)) = w;
}

__device__ __forceinline__ void arrive(int* cnt, int* flag, int target)
{
    __threadfence();
    int old = atomicAdd(cnt, 1);
    if (old == target * RCTA - 1)
        asm volatile("st.global.release.gpu.s32 [%0], %1;" :: "l"(flag), "r"(target) : "memory");
}

__global__ __launch_bounds__(256, 1) void gru_rec_kernel(
    const float* __restrict__ Wh, const float* __restrict__ bh,
    float* __restrict__ hiddens)
{
    unsigned* Whs = rec_smem;                        // [kb64][gate3][jh2][lane32][2]
    float* redA = (float*)(rec_smem + 24576);        // [s3][r64][25]
    float* redB = redA + 4800;
    const int tid  = threadIdx.x;
    const int lane = tid & 31;
    const int warp = tid >> 5;
    const int mt = warp & 1;        // m-tile (16 rows within the 32-row half)
    const int kh = warp >> 1;       // K quarter (0..3)
    const int g = lane >> 2, c = lane & 3;
    const int bid = blockIdx.x;
    const int j0 = bid * RJ;

    // Load Wh slice -> SMEM in fp16 B-fragment order, once.
    for (int flat = tid; flat < 64 * 6 * 32; flat += 256) {
        int kb = flat / 192, rem = flat % 192;
        int gi = rem >> 6;
        int jh = (rem >> 5) & 1;
        int ln = rem & 31;
        int gg = ln >> 2, cc = ln & 3;
        const float* wp = Wh + (size_t)(gi * HDIM + j0 + jh * 8 + gg) * HDIM + kb * 16 + 2 * cc;
        Whs[flat * 2 + 0] = packh2(wp[0], wp[1]);
        Whs[flat * 2 + 1] = packh2(wp[8], wp[9]);
    }

    float bhv[3][2][2];
#pragma unroll
    for (int gi = 0; gi < 3; gi++)
#pragma unroll
        for (int jh = 0; jh < 2; jh++) {
            int jj = j0 + jh * 8 + 2 * c;
            bhv[gi][jh][0] = bh[gi * HDIM + jj];
            bhv[gi][jh][1] = bh[gi * HDIM + jj + 1];
        }

    // Per-stream epilogue state (kh==0 warps). Batch rows: A half base 0, B half base 32.
    const int a0 = mt * 16 + g,      a1 = a0 + 8;        // stream A global rows
    const int b0 = 32 + mt * 16 + g, b1 = b0 + 8;        // stream B global rows
    EpiState stA, stB;
#pragma unroll
    for (int jh = 0; jh < 2; jh++)
#pragma unroll
        for (int e = 0; e < 4; e++) { stA.hpr[jh][e] = 0.0f; stB.hpr[jh][e] = 0.0f; }
    if (kh == 0) {
        load_x(0, a0, a1, j0, c, stA.xv);
        load_x(0, b0, b1, j0, c, stB.xv);
    }

    __syncthreads();

    for (int t = 0; t < TDIM; t++) {
        float acc[3][2][4];
        float hy[2][4];

        // ===================== stream A: step t =====================
        mma_phase(g_hfA[t & 1], Whs, mt, kh, lane, acc);
        if (kh) {
            float* rp = redA + ((kh - 1) * 64 + mt * 32 + lane) * 25;
#pragma unroll
            for (int gi = 0; gi < 3; gi++)
#pragma unroll
                for (int jh = 0; jh < 2; jh++)
#pragma unroll
                    for (int e = 0; e < 4; e++) rp[gi * 8 + jh * 4 + e] = acc[gi][jh][e];
        }
        __syncthreads();                               // S1: redA complete

        if (kh == 0) {
            epilogue(acc, redA, stA, bhv, mt, lane, g_hfA[(t + 1) & 1], bid, c, hy);
            asm volatile("bar.sync 1, 64;" ::: "memory");
            if (tid == 0) arrive(&g_sync[0], &g_sync[32], t + 1);
            // slack work: hiddens A + next xA
#pragma unroll
            for (int jh = 0; jh < 2; jh++) {
                int jj = j0 + jh * 8 + 2 * c;
                *(float2*)&hiddens[((size_t)a0 * TDIM + t) * HDIM + jj] = make_float2(hy[jh][0], hy[jh][1]);
                *(float2*)&hiddens[((size_t)a1 * TDIM + t) * HDIM + jj] = make_float2(hy[jh][2], hy[jh][3]);
            }
            if (t + 1 < TDIM) load_x(t + 1, a0, a1, j0, c, stA.xv);
        } else if (tid == 96) {
            // gate for MMA_B(t): h^B_t published (flagB >= t)
            while (ld_acq(&g_sync[96]) < t) __nanosleep(20);
        }
        asm volatile("bar.sync 2, 256;" ::: "memory"); // everyone: h^B_t visible

        // ===================== stream B: step t =====================
        mma_phase(g_hfB[t & 1], Whs, mt, kh, lane, acc);
        if (kh) {
            float* rp = redB + ((kh - 1) * 64 + mt * 32 + lane) * 25;
#pragma unroll
            for (int gi = 0; gi < 3; gi++)
#pragma unroll
                for (int jh = 0; jh < 2; jh++)
#pragma unroll
                    for (int e = 0; e < 4; e++) rp[gi * 8 + jh * 4 + e] = acc[gi][jh][e];
        }
        __syncthreads();                               // S2: redB complete

        if (kh == 0) {
            epilogue(acc, redB, stB, bhv, mt, lane, g_hfB[(t + 1) & 1], bid, c, hy);
            asm volatile("bar.sync 1, 64;" ::: "memory");
            if (tid == 0) arrive(&g_sync[64], &g_sync[96], t + 1);
#pragma unroll
            for (int jh = 0; jh < 2; jh++) {
                int jj = j0 + jh * 8 + 2 * c;
                *(float2*)&hiddens[((size_t)b0 * TDIM + t) * HDIM + jj] = make_float2(hy[jh][0], hy[jh][1]);
                *(float2*)&hiddens[((size_t)b1 * TDIM + t) * HDIM + jj] = make_float2(hy[jh][2], hy[jh][3]);
            }
            if (t + 1 < TDIM) load_x(t + 1, b0, b1, j0, c, stB.xv);
        } else if (tid == 64) {
            // gate for MMA_A(t+1): h^A_{t+1} published (flagA >= t+1)
            while (ld_acq(&g_sync[32]) < t + 1) __nanosleep(20);
        }
        asm volatile("bar.sync 3, 256;" ::: "memory"); // everyone: h^A_{t+1} visible
    }
}

__global__ void rec_init_kernel() {
    int i = blockIdx.x * blockDim.x + threadIdx.x;
    if (i < 128) g_sync[i] = 0;
    if (i < 16384) { g_hfA[0][i] = 0u; g_hfB[0][i] = 0u; }
}

extern "C" void kernel_launch(void* const* d_in, const int* in_sizes, int n_in,
                              void* d_out, int out_size)
{
    (void)in_sizes; (void)n_in; (void)out_size;
    const float* inputs = (const float*)d_in[0];
    const float* Wx = (const float*)d_in[1];
    const float* bx = (const float*)d_in[2];
    const float* Wh = (const float*)d_in[3];
    const float* bh = (const float*)d_in[4];
    const float* Wo = (const float*)d_in[5];
    const float* bo = (const float*)d_in[6];

    float* hiddens = (float*)d_out;                       // (B,T,H)
    float* proj    = hiddens + (size_t)MROWS * HDIM;      // (B,T,O)

    float* xall = nullptr;
    cudaGetSymbolAddress((void**)&xall, g_xall);

    // ncu alignment (harness pre-injects 2 launches; REC lands at -s 5 -c 1)
    dummy_kernel<<<1, 32>>>();

    // Phase 0: reset flags + zero h0 fragments (every launch/replay)
    rec_init_kernel<<<256, 256>>>();

    // Phase 1: x_all = inputs @ Wx^T + bx   (M=32768, N=3072, K=512)
    gemm_nt_kernel<<<dim3(G3 / 128, MROWS / 128), 256>>>(inputs, Wx, bx, xall, G3, DDIM);

    // Phase 2: persistent GRU recurrence -> hiddens (in d_out)
    const int rec_smem_bytes = 24576 * 4 + 9600 * 4;      // 136,704 B
    cudaFuncSetAttribute(gru_rec_kernel, cudaFuncAttributeMaxDynamicSharedMemorySize, rec_smem_bytes);
    gru_rec_kernel<<<RCTA, 256, rec_smem_bytes>>>(Wh, bh, hiddens);

    // Phase 3: out = hiddens @ Wo^T + bo   (M=32768, N=512, K=1024)
    gemm_nt_kernel<<<dim3(ODIM / 128, MROWS / 128), 256>>>(hiddens, Wo, bo, proj, ODIM, HDIM);
}